// round 14
// baseline (speedup 1.0000x reference)
#include <cuda_runtime.h>
#include <cuda_bf16.h>
#include <math.h>

#define T_STEPS 300
#define DIN 39
#define H1D 35
#define H2D 30
#define BT 64
#define BATCH 4096
#define NBLK (BATCH/BT)
#define NT 416           // 6 L1 warps + 6 L2 warps + 1 stager

#define KP 88            // row stride (bf16): (row*44+tq)%32 covers all banks -> conflict-free
#define N1 144           // L1 gate cols (36 units * 4)
#define N2 128           // L2 gate cols (32 units * 4)

// smem byte offsets (all 16B aligned)
#define B1_OFF   0
#define B2_OFF   576
#define W1H_OFF  1088
#define W1L_OFF  26432
#define W2H_OFF  51776
#define W2L_OFF  74304
#define A1H_OFF  96832     // 2 buffers of 64*KP u16 (11264 B each)
#define A1L_OFF  119360
#define A2H_OFF  141888
#define A2L_OFF  164416
#define SMEM_BYTES 186944
#define ABUF (64*KP)       // u16 elements per A buffer

typedef unsigned long long ull;
typedef unsigned short u16;
typedef unsigned int u32;

// scratch: LSTM hidden states [T][60][B]  (fw units [0,30), bw [30,60))
__device__ float g_hbuf[(size_t)BATCH * T_STEPS * 60];
// pre-split transposed input, A-operand layout [T][btile][64 rows][40 cols]
__device__ u16 g_xhi[(size_t)T_STEPS * NBLK * 64 * 40];
__device__ u16 g_xlo[(size_t)T_STEPS * NBLK * 64 * 40];

// ---------------- helpers ----------------
__device__ __forceinline__ ull fma2(ull a, ull b, ull c) {
    ull d;
    asm("fma.rn.f32x2 %0, %1, %2, %3;" : "=l"(d) : "l"(a), "l"(b), "l"(c));
    return d;
}
__device__ __forceinline__ ull pack2(float lo, float hi) {
    ull d;
    asm("mov.b64 %0, {%1, %2};" : "=l"(d) : "f"(lo), "f"(hi));
    return d;
}
__device__ __forceinline__ void unpack2(ull v, float& lo, float& hi) {
    asm("mov.b64 {%0, %1}, %2;" : "=f"(lo), "=f"(hi) : "l"(v));
}
__device__ __forceinline__ float sigf(float x) {
    return __fdividef(1.0f, 1.0f + __expf(-x));
}
__device__ __forceinline__ float tanhfast(float x) {
    return 2.0f * sigf(2.0f * x) - 1.0f;
}
__device__ __forceinline__ float cellone(float zi, float zj, float zf, float zo, float& c) {
    c = sigf(zf + 1.0f) * c + sigf(zi) * tanhfast(zj);
    return sigf(zo) * tanhfast(c);
}
__device__ __forceinline__ void bsplit(float v, u16& hi, u16& lo) {
    __nv_bfloat16 h = __float2bfloat16(v);
    float r = v - __bfloat162float(h);
    __nv_bfloat16 l = __float2bfloat16(r);
    hi = __bfloat16_as_ushort(h);
    lo = __bfloat16_as_ushort(l);
}

__device__ __forceinline__ void mma16816(float& c0, float& c1, float& c2, float& c3,
                                         u32 a0, u32 a1, u32 a2, u32 a3,
                                         u32 b0, u32 b1)
{
    asm volatile("mma.sync.aligned.m16n8k16.row.col.f32.bf16.bf16.f32 "
                 "{%0,%1,%2,%3},{%4,%5,%6,%7},{%8,%9},{%0,%1,%2,%3};"
                 : "+f"(c0), "+f"(c1), "+f"(c2), "+f"(c3)
                 : "r"(a0), "r"(a1), "r"(a2), "r"(a3), "r"(b0), "r"(b1));
}

// Fused MMA + cell for one warp covering TWO m-tiles (mi0, mi0+1) and n-tiles
// n0..n0+NCNT. W regs are loaded once per (kc, nt) and reused across both
// m-tiles (halves W crossbar traffic vs the 1-m-tile version).
// 3-product bf16 split GEMM (K=80) -> shfl gate exchange -> in-register cell
// -> bf16-split h write to A buffers (and optionally g_hbuf).
// cst holds NCNT*2 cell states: cst[nt*2 + mm].
template<int NCNT>
__device__ __forceinline__ void mma_cell2(
    const u16* __restrict__ Ah, const u16* __restrict__ Al,
    const u16* __restrict__ Wh, const u16* __restrict__ Wl,
    const float* __restrict__ bias, float* __restrict__ cst,
    u16* dA1h, u16* dA1l,            // null for L2
    u16* dA2h, u16* dA2l, int colbase,
    float* ghb,                       // null unless L2 (base for this tick)
    int mi0, int n0, int lane)
{
    const int g  = lane >> 2;
    const int tq = lane & 3;
    const int t2 = tq * 2;
    float acc[NCNT][2][4];
    #pragma unroll
    for (int i = 0; i < NCNT; ++i)
        #pragma unroll
        for (int m = 0; m < 2; ++m) {
            acc[i][m][0] = 0.f; acc[i][m][1] = 0.f;
            acc[i][m][2] = 0.f; acc[i][m][3] = 0.f;
        }

    #pragma unroll
    for (int kc = 0; kc < 5; ++kc) {
        const int ka = kc * 16;
        u32 ah[2][4], al[2][4];
        #pragma unroll
        for (int mm = 0; mm < 2; ++mm) {
            const int ar0 = ((mi0 + mm)*16 + g)*KP + t2;
            const int ar1 = ar0 + 8*KP;
            ah[mm][0] = *(const u32*)(Ah + ar0 + ka);
            ah[mm][1] = *(const u32*)(Ah + ar1 + ka);
            ah[mm][2] = *(const u32*)(Ah + ar0 + ka + 8);
            ah[mm][3] = *(const u32*)(Ah + ar1 + ka + 8);
            al[mm][0] = *(const u32*)(Al + ar0 + ka);
            al[mm][1] = *(const u32*)(Al + ar1 + ka);
            al[mm][2] = *(const u32*)(Al + ar0 + ka + 8);
            al[mm][3] = *(const u32*)(Al + ar1 + ka + 8);
        }
        #pragma unroll
        for (int nt = 0; nt < NCNT; ++nt) {
            const int wr = ((n0 + nt)*8 + g)*KP + t2 + ka;
            u32 bh0 = *(const u32*)(Wh + wr);
            u32 bh1 = *(const u32*)(Wh + wr + 8);
            u32 bl0 = *(const u32*)(Wl + wr);
            u32 bl1 = *(const u32*)(Wl + wr + 8);
            #pragma unroll
            for (int mm = 0; mm < 2; ++mm) {
                mma16816(acc[nt][mm][0],acc[nt][mm][1],acc[nt][mm][2],acc[nt][mm][3],
                         ah[mm][0],ah[mm][1],ah[mm][2],ah[mm][3], bh0,bh1);
                mma16816(acc[nt][mm][0],acc[nt][mm][1],acc[nt][mm][2],acc[nt][mm][3],
                         ah[mm][0],ah[mm][1],ah[mm][2],ah[mm][3], bl0,bl1);
                mma16816(acc[nt][mm][0],acc[nt][mm][1],acc[nt][mm][2],acc[nt][mm][3],
                         al[mm][0],al[mm][1],al[mm][2],al[mm][3], bh0,bh1);
            }
        }
    }

    const int odd = tq & 1;
    #pragma unroll
    for (int nt = 0; nt < NCNT; ++nt) {
        const int C = (n0 + nt) * 8;
        const int u = 2*(n0 + nt) + (tq >> 1);
        const float4 bb = *(const float4*)(bias + C + ((tq & 2) << 1));
        #pragma unroll
        for (int mm = 0; mm < 2; ++mm) {
            const int row = ((mi0 + mm)*16) + (odd ? 8 : 0) + g;
            float s0 = odd ? acc[nt][mm][0] : acc[nt][mm][2];
            float s1 = odd ? acc[nt][mm][1] : acc[nt][mm][3];
            float e0 = __shfl_xor_sync(0xffffffffu, s0, 1);
            float e1 = __shfl_xor_sync(0xffffffffu, s1, 1);
            float zi, zj, zf, zo;
            if (odd) { zi = e0;             zj = e1;             zf = acc[nt][mm][2]; zo = acc[nt][mm][3]; }
            else     { zi = acc[nt][mm][0]; zj = acc[nt][mm][1]; zf = e0;             zo = e1;             }
            float h = cellone(zi + bb.x, zj + bb.y, zf + bb.z, zo + bb.w, cst[nt*2 + mm]);
            u16 hh, hl; bsplit(h, hh, hl);
            const int idx = row*KP + colbase + u;
            dA2h[idx] = hh;
            dA2l[idx] = hl;
            if (dA1h) { dA1h[row*KP + u] = hh; dA1l[row*KP + u] = hl; }
            if (ghb && u < H2D) ghb[(size_t)u * BATCH + row] = h;
        }
    }
}

// ============ x prep: [B][T][D] fp32 -> [T][btile][64][40] bf16 hi/lo ============
#define TT 256
__global__ void __launch_bounds__(TT)
xsplit_kernel(const float* __restrict__ x)
{
    __shared__ float s[DIN * 65];
    const int t  = blockIdx.x;
    const int bt = blockIdx.y;
    const int b0 = bt * 64;
    const int tid = threadIdx.x;

    for (int i = tid; i < 64 * DIN; i += TT) {
        int b = i / DIN, d = i - b * DIN;
        s[d * 65 + b] = x[((size_t)(b0 + b) * T_STEPS + t) * DIN + d];
    }
    __syncthreads();
    const size_t base = ((size_t)t * NBLK + bt) * 2560;
    for (int i = tid; i < 2560; i += TT) {
        int b = i / 40, d = i - b * 40;
        float v = (d < DIN) ? s[d * 65 + b] : 0.f;
        u16 hi, lo; bsplit(v, hi, lo);
        g_xhi[base + i] = hi;
        g_xlo[base + i] = lo;
    }
}

// =============================== LSTM kernel ===============================
extern __shared__ char smc[];

__global__ void __launch_bounds__(NT)
lstm_kernel(const float* __restrict__ fw_W1, const float* __restrict__ fw_b1,
            const float* __restrict__ fw_W2, const float* __restrict__ fw_b2,
            const float* __restrict__ bw_W1, const float* __restrict__ bw_b1,
            const float* __restrict__ bw_W2, const float* __restrict__ bw_b2)
{
    const int dir = blockIdx.y;
    const int bti = blockIdx.x;
    const int b0g = bti * BT;
    const int tid = threadIdx.x;

    float* b1s = (float*)(smc + B1_OFF);
    float* b2s = (float*)(smc + B2_OFF);
    u16* W1h = (u16*)(smc + W1H_OFF);
    u16* W1l = (u16*)(smc + W1L_OFF);
    u16* W2h = (u16*)(smc + W2H_OFF);
    u16* W2l = (u16*)(smc + W2L_OFF);
    u16* A1h = (u16*)(smc + A1H_OFF);   // [2][64*KP]
    u16* A1l = (u16*)(smc + A1L_OFF);
    u16* A2h = (u16*)(smc + A2H_OFF);
    u16* A2l = (u16*)(smc + A2L_OFF);

    const float* W1g = dir ? bw_W1 : fw_W1;
    const float* b1g = dir ? bw_b1 : fw_b1;
    const float* W2g = dir ? bw_W2 : fw_W2;
    const float* b2g = dir ? bw_b2 : fw_b2;

    // ---- prologue ----
    for (int i = tid; i < 2*ABUF; i += NT) { A1h[i]=0; A1l[i]=0; A2h[i]=0; A2l[i]=0; }

    // W1: n-major cols 0..143 (unit-major gates); k-rows: 0..34 h1, 35 pad, 36..74 x, 75..87 pad
    for (int i = tid; i < N1*KP; i += NT) {
        int n = i / KP, c = i - n * KP;
        int u = n >> 2, gg = n & 3;
        float v = 0.f;
        if (u < H1D) {
            int col = gg*H1D + u;
            int kr = -1;
            if (c < H1D) kr = 39 + c;
            else if (c >= 36 && c < 36 + DIN) kr = c - 36;
            if (kr >= 0) v = W1g[kr*140 + col];
        }
        u16 hi, lo; bsplit(v, hi, lo);
        W1h[i] = hi; W1l[i] = lo;
    }
    // W2: cols 0..127; k-rows: 0..34 h1, 35 pad, 36..65 h2, 66..87 pad
    for (int i = tid; i < N2*KP; i += NT) {
        int n = i / KP, c = i - n * KP;
        int u = n >> 2, gg = n & 3;
        float v = 0.f;
        if (u < H2D) {
            int col = gg*H2D + u;
            int kr = -1;
            if (c < H1D) kr = c;
            else if (c >= 36 && c < 36 + H2D) kr = H1D + (c - 36);
            if (kr >= 0) v = W2g[kr*120 + col];
        }
        u16 hi, lo; bsplit(v, hi, lo);
        W2h[i] = hi; W2l[i] = lo;
    }
    for (int i = tid; i < N1; i += NT) {
        int u = i >> 2, gg = i & 3;
        b1s[i] = (u < H1D) ? b1g[gg*H1D + u] : 0.f;
    }
    for (int i = tid; i < N2; i += NT) {
        int u = i >> 2, gg = i & 3;
        b2s[i] = (u < H2D) ? b2g[gg*H2D + u] : 0.f;
    }
    // stage x[0] into A1 buffer 1 (= read buffer of tick 0)
    {
        const int tx0 = dir ? (T_STEPS - 1) : 0;
        const size_t base = ((size_t)tx0 * NBLK + bti) * 2560;
        for (int i = tid; i < 2560; i += NT) {
            int r = i / 40, d = i - r * 40;
            A1h[ABUF + r*KP + 36 + d] = g_xhi[base + i];
            A1l[ABUF + r*KP + 36 + d] = g_xlo[base + i];
        }
    }
    __syncthreads();

    const int warp = tid >> 5, lane = tid & 31;
    float cst[12];
    #pragma unroll
    for (int i = 0; i < 12; ++i) cst[i] = 0.f;

    // roles: warps 0..5  = L1: mg = w&1 (mi0 = mg*2), ngp = w>>1 (n0 = ngp*6, NCNT=6)
    //        warps 6..11 = L2: w2 = w-6, mg = w2&1, ngp = w2>>1 (NCNT 6,5,5; n0 0,6,11)
    //        warp 12 = x stager
    for (int tk = 0; tk <= T_STEPS; ++tk) {
        const int wb = tk & 1, rb = wb ^ 1;

        if (warp < 6) {
            if (tk < T_STEPS) {
                const int mi0 = (warp & 1) * 2, ngp = warp >> 1;
                mma_cell2<6>(A1h + rb*ABUF, A1l + rb*ABUF, W1h, W1l,
                             b1s, cst,
                             A1h + wb*ABUF, A1l + wb*ABUF,
                             A2h + wb*ABUF, A2l + wb*ABUF, 0,
                             (float*)0, mi0, ngp*6, lane);
            }
        } else if (warp < 12) {
            if (tk >= 1) {
                const int w2 = warp - 6;
                const int mi0 = (w2 & 1) * 2, ngp = w2 >> 1;
                const int tx = dir ? (T_STEPS - tk) : (tk - 1);
                float* ghb = g_hbuf + ((size_t)(tx*60 + dir*H2D))*BATCH + b0g;
                if (ngp == 0)
                    mma_cell2<6>(A2h + rb*ABUF, A2l + rb*ABUF, W2h, W2l,
                                 b2s, cst, (u16*)0, (u16*)0,
                                 A2h + wb*ABUF, A2l + wb*ABUF, 36,
                                 ghb, mi0, 0, lane);
                else if (ngp == 1)
                    mma_cell2<5>(A2h + rb*ABUF, A2l + rb*ABUF, W2h, W2l,
                                 b2s, cst, (u16*)0, (u16*)0,
                                 A2h + wb*ABUF, A2l + wb*ABUF, 36,
                                 ghb, mi0, 6, lane);
                else
                    mma_cell2<5>(A2h + rb*ABUF, A2l + rb*ABUF, W2h, W2l,
                                 b2s, cst, (u16*)0, (u16*)0,
                                 A2h + wb*ABUF, A2l + wb*ABUF, 36,
                                 ghb, mi0, 11, lane);
            }
        } else {
            if (tk + 1 < T_STEPS) {
                // stage x[tk+1] into A1[wb] x-region (read next tick)
                const int txn = dir ? (T_STEPS - 2 - tk) : (tk + 1);
                const size_t base = ((size_t)txn * NBLK + bti) * 2560;
                u16* dh = A1h + wb*ABUF;
                u16* dl = A1l + wb*ABUF;
                for (int i = lane; i < 640; i += 32) {
                    int r = i / 10, c = i - r * 10;
                    ((ull*)(dh + r*KP + 36))[c] = ((const ull*)(g_xhi + base + r*40))[c];
                    ((ull*)(dl + r*KP + 36))[c] = ((const ull*)(g_xlo + base + r*40))[c];
                }
            }
        }
        __syncthreads();
    }
}

// =============================== FC head (unchanged, passing) ===============================
#define FCT 128
#define FOFF_W1 0
#define FOFF_W2 (FOFF_W1 + 60*52)
#define FOFF_W3 (FOFF_W2 + 50*40)
#define FOFF_B1 (FOFF_W3 + 80)
#define FOFF_B2 (FOFF_B1 + 52)
#define FOFF_B3 (FOFF_B2 + 40)
#define FSM_FLOATS (FOFF_B3 + 4)

__global__ void __launch_bounds__(FCT)
fc_kernel(const float* __restrict__ Wf1, const float* __restrict__ bf1,
          const float* __restrict__ Wf2, const float* __restrict__ bf2,
          const float* __restrict__ Wf3, const float* __restrict__ bf3,
          float* __restrict__ out)
{
    extern __shared__ float fsm[];
    float* W1s = fsm + FOFF_W1;
    float* W2s = fsm + FOFF_W2;
    float* W3s = fsm + FOFF_W3;
    float* B1s = fsm + FOFF_B1;
    float* B2s = fsm + FOFF_B2;
    float* B3s = fsm + FOFF_B3;

    const int tid = threadIdx.x;

    for (int i = tid; i < 60*52; i += FCT) {
        int k = i / 52, j = i - k * 52;
        W1s[i] = (j < 50) ? Wf1[k*50 + j] : 0.f;
    }
    for (int i = tid; i < 50*40; i += FCT) W2s[i] = Wf2[i];
    for (int i = tid; i < 80;    i += FCT) W3s[i] = Wf3[i];
    for (int i = tid; i < 52;    i += FCT) B1s[i] = (i < 50) ? bf1[i] : 0.f;
    for (int i = tid; i < 40;    i += FCT) B2s[i] = bf2[i];
    for (int i = tid; i < 2;     i += FCT) B3s[i] = bf3[i];
    __syncthreads();

    const int bi = blockIdx.x & 31;
    const int t  = blockIdx.x >> 5;
    const int b0 = bi * FCT;
    const float* __restrict__ hb = &g_hbuf[(size_t)t * 60 * BATCH + b0 + tid];

    ull acc1[26];
    #pragma unroll
    for (int j = 0; j < 26; ++j) acc1[j] = pack2(B1s[2*j], B1s[2*j+1]);
    #pragma unroll 4
    for (int k = 0; k < 60; ++k) {
        float v = hb[(size_t)k * BATCH];
        ull vv = pack2(v, v);
        #pragma unroll
        for (int j = 0; j < 13; ++j) {
            ulonglong2 w = *(const ulonglong2*)(W1s + k*52 + j*4);
            acc1[2*j]   = fma2(vv, w.x, acc1[2*j]);
            acc1[2*j+1] = fma2(vv, w.y, acc1[2*j+1]);
        }
    }
    float a1[52];
    #pragma unroll
    for (int j = 0; j < 26; ++j) {
        float lo, hi; unpack2(acc1[j], lo, hi);
        a1[2*j]   = fmaxf(lo, 0.f);
        a1[2*j+1] = fmaxf(hi, 0.f);
    }

    ull acc2[20];
    #pragma unroll
    for (int j = 0; j < 20; ++j) acc2[j] = pack2(B2s[2*j], B2s[2*j+1]);
    #pragma unroll 5
    for (int k = 0; k < 50; ++k) {
        ull vv = pack2(a1[k], a1[k]);
        #pragma unroll
        for (int j = 0; j < 10; ++j) {
            ulonglong2 w = *(const ulonglong2*)(W2s + k*40 + j*4);
            acc2[2*j]   = fma2(vv, w.x, acc2[2*j]);
            acc2[2*j+1] = fma2(vv, w.y, acc2[2*j+1]);
        }
    }
    float a2[40];
    #pragma unroll
    for (int j = 0; j < 20; ++j) {
        float lo, hi; unpack2(acc2[j], lo, hi);
        a2[2*j]   = fmaxf(lo, 0.f);
        a2[2*j+1] = fmaxf(hi, 0.f);
    }

    float o0 = B3s[0], o1 = B3s[1];
    #pragma unroll
    for (int k = 0; k < 40; ++k) {
        o0 = fmaf(a2[k], W3s[2*k + 0], o0);
        o1 = fmaf(a2[k], W3s[2*k + 1], o1);
    }
    float2 ov = make_float2(o0, o1);
    *(float2*)(&out[((size_t)(b0 + tid) * T_STEPS + t) * 2]) = ov;
}

// ============================================================================
extern "C" void kernel_launch(void* const* d_in, const int* in_sizes, int n_in,
                              void* d_out, int out_size)
{
    const float* x     = (const float*)d_in[0];
    const float* fw_W1 = (const float*)d_in[1];
    const float* fw_b1 = (const float*)d_in[2];
    const float* fw_W2 = (const float*)d_in[3];
    const float* fw_b2 = (const float*)d_in[4];
    const float* bw_W1 = (const float*)d_in[5];
    const float* bw_b1 = (const float*)d_in[6];
    const float* bw_W2 = (const float*)d_in[7];
    const float* bw_b2 = (const float*)d_in[8];
    const float* Wf1   = (const float*)d_in[9];
    const float* bf1   = (const float*)d_in[10];
    const float* Wf2   = (const float*)d_in[11];
    const float* bf2   = (const float*)d_in[12];
    const float* Wf3   = (const float*)d_in[13];
    const float* bf3   = (const float*)d_in[14];

    cudaFuncSetAttribute(lstm_kernel, cudaFuncAttributeMaxDynamicSharedMemorySize,
                         SMEM_BYTES);
    cudaFuncSetAttribute(fc_kernel, cudaFuncAttributeMaxDynamicSharedMemorySize,
                         FSM_FLOATS * (int)sizeof(float));

    xsplit_kernel<<<dim3(T_STEPS, NBLK), TT>>>(x);

    lstm_kernel<<<dim3(NBLK, 2), NT, SMEM_BYTES>>>(
        fw_W1, fw_b1, fw_W2, fw_b2, bw_W1, bw_b1, bw_W2, bw_b2);

    fc_kernel<<<32 * T_STEPS, FCT, FSM_FLOATS * sizeof(float)>>>(
        Wf1, bf1, Wf2, bf2, Wf3, bf3, (float*)d_out);
}